// round 13
// baseline (speedup 1.0000x reference)
#include <cuda_runtime.h>
#include <cuda_fp16.h>
#include <cstdint>

#define N_NODES 10000
#define N_EDGES 320000
#define F_IN 512
#define HID 256
#define M_PAD 10112
#define BKT 128

// ---------------- device scratch ----------------
__device__ __align__(16) int   g_pos[N_NODES];   // bucket fill ctr; zero at load; re-zeroed by fusedU
__device__ __align__(16) int   g_deg[N_NODES];   // indegree (REDG);  zero at load; re-zeroed by fusedU
__device__ __align__(16) int   g_bkt[(size_t)N_NODES * BKT];
__device__ __align__(16) __half g_H0h[(size_t)N_NODES * HID];  // (H0+b1)*rdeg, fp16
__device__ __align__(16) float g_Z[N_NODES * 2];
__device__ __align__(16) __half g_Af[(size_t)M_PAD * F_IN];    // feature fp16
__device__ __align__(16) __half g_Bf[HID * F_IN];              // W1^T fp16 [n][k]

// ---------------- static-init stream/event resources ----------------
struct ForkRes {
    cudaStream_t s = nullptr;
    cudaEvent_t e1 = nullptr, e2 = nullptr;
    bool ok = false;
    ForkRes() {
        if (cudaStreamCreateWithFlags(&s, cudaStreamNonBlocking) == cudaSuccess &&
            cudaEventCreateWithFlags(&e1, cudaEventDisableTiming) == cudaSuccess &&
            cudaEventCreateWithFlags(&e2, cudaEventDisableTiming) == cudaSuccess)
            ok = true;
    }
};
static ForkRes g_fork;

// ---------------- helpers ----------------
#define LDSM_X4(r0, r1, r2, r3, addr) \
    asm volatile("ldmatrix.sync.aligned.m8n8.x4.shared.b16 {%0,%1,%2,%3}, [%4];" \
        : "=r"(r0), "=r"(r1), "=r"(r2), "=r"(r3) : "r"(addr))
#define LDSM_X2(r0, r1, addr) \
    asm volatile("ldmatrix.sync.aligned.m8n8.x2.shared.b16 {%0,%1}, [%2];" \
        : "=r"(r0), "=r"(r1) : "r"(addr))
#define MMA_F16(d0, d1, d2, d3, a0, a1, a2, a3, b0, b1) \
    asm volatile("mma.sync.aligned.m16n8k16.row.col.f32.f16.f16.f32 " \
        "{%0,%1,%2,%3}, {%4,%5,%6,%7}, {%8,%9}, {%0,%1,%2,%3};" \
        : "+f"(d0), "+f"(d1), "+f"(d2), "+f"(d3) \
        : "r"(a0), "r"(a1), "r"(a2), "r"(a3), "r"(b0), "r"(b1))
#define CP16(saddr, gptr) \
    asm volatile("cp.async.cg.shared.global [%0], [%1], 16;" :: "r"(saddr), "l"(gptr))
#define CP_COMMIT() asm volatile("cp.async.commit_group;" ::: "memory")
#define CP_WAIT1()  asm volatile("cp.async.wait_group 1;" ::: "memory")

// ---------------- degree (REDG: no return value used) ----------------
__global__ void deg_kernel(const int* __restrict__ ei) {
    int e = blockIdx.x * blockDim.x + threadIdx.x;
    if (e >= N_EDGES) return;
    atomicAdd(&g_deg[ei[N_EDGES + e]], 1);
}

// ---------------- bucket scatter ----------------
__global__ void scatter_kernel(const int* __restrict__ ei) {
    int e = blockIdx.x * blockDim.x + threadIdx.x;
    if (e >= N_EDGES) return;
    int s = ei[e];
    int d = ei[N_EDGES + e];
    int pos = atomicAdd(&g_pos[d], 1);
    if (pos < BKT) g_bkt[(size_t)d * BKT + pos] = s;
}

// ---------------- prep: fp16 A + transpose fp16 W1 ----------------
__global__ void prep_kernel(const float* __restrict__ A, const float* __restrict__ W1) {
    int tid = blockIdx.x * blockDim.x + threadIdx.x;
    if (tid < (N_NODES * F_IN) / 8) {
        int idx8 = tid * 8;
        const float* p = A + idx8;
        float4 v0 = *(const float4*)p;
        float4 v1 = *(const float4*)(p + 4);
        uint32_t w[4];
        __half2 h;
        h = __floats2half2_rn(v0.x, v0.y); w[0] = *(uint32_t*)&h;
        h = __floats2half2_rn(v0.z, v0.w); w[1] = *(uint32_t*)&h;
        h = __floats2half2_rn(v1.x, v1.y); w[2] = *(uint32_t*)&h;
        h = __floats2half2_rn(v1.z, v1.w); w[3] = *(uint32_t*)&h;
        *(uint4*)(g_Af + idx8) = make_uint4(w[0], w[1], w[2], w[3]);
    }
    if (tid < (F_IN * HID) / 8) {
        int n = tid & 255;
        int kb = (tid >> 8) * 8;
        uint32_t w[4];
        #pragma unroll
        for (int q = 0; q < 4; q++) {
            float x0 = W1[(size_t)(kb + 2 * q) * HID + n];
            float x1 = W1[(size_t)(kb + 2 * q + 1) * HID + n];
            __half2 h = __floats2half2_rn(x0, x1);
            w[q] = *(uint32_t*)&h;
        }
        *(uint4*)(g_Bf + (size_t)n * F_IN + kb) = make_uint4(w[0], w[1], w[2], w[3]);
    }
}

// ---------------- HMMA fp16 GEMM: CTA tile 64x128, grid (2,157) ----------------
#define ROWB 80
#define S_A 0
#define S_B 5120
#define STG 15360

__global__ __launch_bounds__(256, 2) void gemm_mma_kernel(const float* __restrict__ bias) {
    extern __shared__ __align__(128) char sm[];
    uint32_t sbase = (uint32_t)__cvta_generic_to_shared(sm);

    const int M = N_NODES;
    int tid = threadIdx.x;
    int wid = tid >> 5;
    int lane = tid & 31;
    int wm = wid >> 2;
    int wn = wid & 3;
    int bm = blockIdx.y * 64;
    int bn = blockIdx.x * 128;

    float acc[2][4][4];
    #pragma unroll
    for (int i = 0; i < 2; i++)
        #pragma unroll
        for (int j = 0; j < 4; j++)
            #pragma unroll
            for (int r = 0; r < 4; r++) acc[i][j][r] = 0.f;

    auto load_stage = [&](int c, int s) {
        int kb = c * 64;
        uint32_t sb = sbase + s * STG;
        const char* gA = (const char*)g_Af + (size_t)bm * 1024 + kb;
        const char* gB = (const char*)g_Bf + (size_t)bn * 1024 + kb;
        {
            int r = tid >> 2, j = tid & 3;
            CP16(sb + S_A + r * ROWB + j * 16, gA + (size_t)r * 1024 + j * 16);
        }
        #pragma unroll
        for (int i = 0; i < 2; i++) {
            int idx = tid + 256 * i;
            int r = idx >> 2, j = idx & 3;
            CP16(sb + S_B + r * ROWB + j * 16, gB + (size_t)r * 1024 + j * 16);
        }
    };

    load_stage(0, 0);
    CP_COMMIT();

    for (int c = 0; c < 16; c++) {
        int s = c & 1;
        if (c + 1 < 16) load_stage(c + 1, (c + 1) & 1);
        CP_COMMIT();
        CP_WAIT1();
        __syncthreads();

        uint32_t stb = sbase + s * STG;
        #pragma unroll
        for (int ks = 0; ks < 2; ks++) {
            int kbyte = ks * 32;
            uint32_t bf[4][2];
            #pragma unroll
            for (int na = 0; na < 4; na++) {
                uint32_t ad = stb + S_B +
                    (uint32_t)((wn * 32 + na * 8 + (lane & 7)) * ROWB + kbyte + ((lane >> 3) & 1) * 16);
                LDSM_X2(bf[na][0], bf[na][1], ad);
            }
            #pragma unroll
            for (int ma = 0; ma < 2; ma++) {
                uint32_t aad = stb + S_A +
                    (uint32_t)((wm * 32 + ma * 16 + (lane & 15)) * ROWB + kbyte + (lane >> 4) * 16);
                uint32_t a0, a1, a2, a3;
                LDSM_X4(a0, a1, a2, a3, aad);
                #pragma unroll
                for (int na = 0; na < 4; na++) {
                    MMA_F16(acc[ma][na][0], acc[ma][na][1], acc[ma][na][2], acc[ma][na][3],
                            a0, a1, a2, a3, bf[na][0], bf[na][1]);
                }
            }
        }
        __syncthreads();
    }

    // epilogue: (acc + bias) * rdeg[row], store fp16   (reads g_deg, not g_pos)
    #pragma unroll
    for (int ma = 0; ma < 2; ma++) {
        int grow0 = bm + wm * 32 + ma * 16 + (lane >> 2);
        int grow1 = grow0 + 8;
        float r0 = (grow0 < M) ? rsqrtf(fmaxf((float)g_deg[grow0], 1.0f)) : 0.f;
        float r1 = (grow1 < M) ? rsqrtf(fmaxf((float)g_deg[grow1], 1.0f)) : 0.f;
        #pragma unroll
        for (int na = 0; na < 4; na++) {
            int col = bn + wn * 32 + na * 8 + (lane & 3) * 2;
            float2 bv = *(const float2*)(bias + col);
            if (grow0 < M) {
                __half2 o = __floats2half2_rn((acc[ma][na][0] + bv.x) * r0,
                                              (acc[ma][na][1] + bv.y) * r0);
                *(__half2*)(g_H0h + (size_t)grow0 * HID + col) = o;
            }
            if (grow1 < M) {
                __half2 o = __floats2half2_rn((acc[ma][na][2] + bv.x) * r1,
                                              (acc[ma][na][3] + bv.y) * r1);
                *(__half2*)(g_H0h + (size_t)grow1 * HID + col) = o;
            }
        }
    }
}

// ---------------- fusedZ: 2 warps per node; pairwise half2 adds ----------------
__global__ __launch_bounds__(256) void fusedZ_kernel(const float* __restrict__ W2,
                                                     const float* __restrict__ b2) {
    __shared__ float sZ[8][2];
    int wid = threadIdx.x >> 5;
    int lane = threadIdx.x & 31;
    int gwarp = blockIdx.x * 8 + wid;
    int node = gwarp >> 1;
    int half = gwarp & 1;
    if (node >= N_NODES) return;

    int cnt = g_pos[node];
    float rdd = rsqrtf(fmaxf((float)cnt, 1.0f));
    if (cnt > BKT) cnt = BKT;
    const int* bkt = g_bkt + (size_t)node * BKT;

    int c0 = half * 128 + 4 * lane;
    float w0[4], w1[4];
    #pragma unroll
    for (int j = 0; j < 4; j++) {
        w0[j] = __ldg(&W2[(c0 + j) * 2 + 0]);
        w1[j] = __ldg(&W2[(c0 + j) * 2 + 1]);
    }
    size_t lane_off = (size_t)half * 128 + 4 * lane;

    float acc[4] = {};
    int p = 0;
    for (; p + 4 <= cnt; p += 4) {
        uint4 idx = *(const uint4*)(bkt + p);
        uint2 v0 = *(const uint2*)(g_H0h + (size_t)idx.x * HID + lane_off);
        uint2 v1 = *(const uint2*)(g_H0h + (size_t)idx.y * HID + lane_off);
        uint2 v2 = *(const uint2*)(g_H0h + (size_t)idx.z * HID + lane_off);
        uint2 v3 = *(const uint2*)(g_H0h + (size_t)idx.w * HID + lane_off);
        // pairwise half2 tree (6 HADD2), convert once, 4 FADD
        __half2 a01x = __hadd2(*(const __half2*)&v0.x, *(const __half2*)&v1.x);
        __half2 a01y = __hadd2(*(const __half2*)&v0.y, *(const __half2*)&v1.y);
        __half2 a23x = __hadd2(*(const __half2*)&v2.x, *(const __half2*)&v3.x);
        __half2 a23y = __hadd2(*(const __half2*)&v2.y, *(const __half2*)&v3.y);
        __half2 ax = __hadd2(a01x, a23x);
        __half2 ay = __hadd2(a01y, a23y);
        float2 fx = __half22float2(ax);
        float2 fy = __half22float2(ay);
        acc[0] += fx.x;
        acc[1] += fx.y;
        acc[2] += fy.x;
        acc[3] += fy.y;
    }
    for (; p < cnt; p++) {
        int s0 = bkt[p];
        uint2 v0 = *(const uint2*)(g_H0h + (size_t)s0 * HID + lane_off);
        float2 f0a = __half22float2(*(const __half2*)&v0.x);
        float2 f0b = __half22float2(*(const __half2*)&v0.y);
        acc[0] += f0a.x;
        acc[1] += f0a.y;
        acc[2] += f0b.x;
        acc[3] += f0b.y;
    }

    float z0 = 0.f, z1 = 0.f;
    #pragma unroll
    for (int j = 0; j < 4; j++) {
        float x = fmaxf(acc[j] * rdd, 0.f);
        z0 += x * w0[j];
        z1 += x * w1[j];
    }
    #pragma unroll
    for (int o = 16; o; o >>= 1) {
        z0 += __shfl_down_sync(0xFFFFFFFFu, z0, o);
        z1 += __shfl_down_sync(0xFFFFFFFFu, z1, o);
    }
    if (lane == 0) {
        sZ[wid][0] = z0;
        sZ[wid][1] = z1;
    }
    __syncthreads();
    if (half == 0 && lane == 0) {
        float t0 = sZ[wid][0] + sZ[wid + 1][0];
        float t1 = sZ[wid][1] + sZ[wid + 1][1];
        g_Z[2 * node + 0] = (t0 + b2[0]) * rdd;   // pre-scale for layer-2 source role
        g_Z[2 * node + 1] = (t1 + b2[1]) * rdd;
    }
}

// ---------------- fusedU + lift + projection; re-zeroes g_pos & g_deg ----------------
__global__ __launch_bounds__(256) void fusedU_kernel(const float* __restrict__ scale,
                                                     float* __restrict__ out) {
    int gw = (blockIdx.x * blockDim.x + threadIdx.x) >> 5;
    int lane = threadIdx.x & 31;
    if (gw >= N_NODES) return;

    int cnt = g_pos[gw];
    float rdd = rsqrtf(fmaxf((float)cnt, 1.0f));
    if (cnt > BKT) cnt = BKT;
    const int* bkt = g_bkt + (size_t)gw * BKT;
    __syncwarp();
    if (lane == 0) {
        g_pos[gw] = 0;   // restore invariants for next call
        g_deg[gw] = 0;
    }

    float u0 = 0.f, u1 = 0.f;
    for (int p = lane; p < cnt; p += 32) {
        int s = bkt[p];
        float2 z = *(const float2*)(g_Z + 2 * s);
        u0 += z.x;
        u1 += z.y;
    }
    #pragma unroll
    for (int o = 16; o; o >>= 1) {
        u0 += __shfl_down_sync(0xFFFFFFFFu, u0, o);
        u1 += __shfl_down_sync(0xFFFFFFFFu, u1, o);
    }
    if (lane == 0) {
        u0 *= rdd;
        u1 *= rdd;
        float un = sqrtf(u0 * u0 + u1 * u1);
        un = fmaxf(un, 1e-15f);
        float ch = coshf(un);
        float sh = sinhf(un);
        float inv = 1.0f / (un * (1.0f + ch));
        float p0 = sh * u0 * inv;
        float p1 = sh * u1 * inv;
        float pn = fmaxf(sqrtf(p0 * p0 + p1 * p1), 1e-12f);
        const float MIN_SCALE = 2.0f * (0.999f / 3.0f);
        const float MAX_SCALE = 0.999f;
        float s = fminf(fmaxf(scale[0], MIN_SCALE), MAX_SCALE);
        p0 = p0 / pn * s;
        p1 = p1 / pn * s;
        float nrm = fmaxf(sqrtf(p0 * p0 + p1 * p1), 1e-15f);
        float maxnorm = 1.0f - 1e-15f;
        if (nrm > maxnorm) {
            p0 = p0 / nrm * maxnorm;
            p1 = p1 / nrm * maxnorm;
        }
        out[2 * gw + 0] = p0;
        out[2 * gw + 1] = p1;
    }
}

// ---------------- launch ----------------
extern "C" void kernel_launch(void* const* d_in, const int* in_sizes, int n_in,
                              void* d_out, int out_size) {
    const float* feature = (const float*)d_in[0];
    const int* ei = (const int*)d_in[1];
    const float* W1 = (const float*)d_in[2];
    const float* b1 = (const float*)d_in[3];
    const float* W2 = (const float*)d_in[4];
    const float* b2 = (const float*)d_in[5];
    const float* scale = (const float*)d_in[6];
    float* out = (float*)d_out;

    cudaFuncSetAttribute(gemm_mma_kernel,
                         cudaFuncAttributeMaxDynamicSharedMemorySize, 2 * STG);

    dim3 gemm_grid(HID / 128, (N_NODES + 63) / 64);   // (2, 157)
    int prep_blocks = ((N_NODES * F_IN / 8) + 255) / 256;
    int edge_blocks = (N_EDGES + 255) / 256;

    if (g_fork.ok) {
        // side stream: deg -> prep -> gemm (gemm only needs degrees, not buckets)
        // main stream: scatter (buckets), concurrently
        cudaEventRecord(g_fork.e1, 0);
        cudaStreamWaitEvent(g_fork.s, g_fork.e1, 0);
        deg_kernel<<<edge_blocks, 256, 0, g_fork.s>>>(ei);
        prep_kernel<<<prep_blocks, 256, 0, g_fork.s>>>(feature, W1);
        gemm_mma_kernel<<<gemm_grid, 256, 2 * STG, g_fork.s>>>(b1);
        cudaEventRecord(g_fork.e2, g_fork.s);

        scatter_kernel<<<edge_blocks, 256>>>(ei);
        cudaStreamWaitEvent(0, g_fork.e2, 0);
    } else {
        deg_kernel<<<edge_blocks, 256>>>(ei);
        prep_kernel<<<prep_blocks, 256>>>(feature, W1);
        scatter_kernel<<<edge_blocks, 256>>>(ei);
        gemm_mma_kernel<<<gemm_grid, 256, 2 * STG>>>(b1);
    }

    fusedZ_kernel<<<(N_NODES * 2 + 7) / 8, 256>>>(W2, b2);
    fusedU_kernel<<<(N_NODES * 32 + 255) / 256, 256>>>(scale, out);
}

// round 14
// speedup vs baseline: 1.0576x; 1.0576x over previous
#include <cuda_runtime.h>
#include <cuda_fp16.h>
#include <cstdint>

#define N_NODES 10000
#define N_EDGES 320000
#define F_IN 512
#define HID 256
#define M_PAD 10112
#define BKT 128

// ---------------- device scratch ----------------
__device__ __align__(16) int   g_pos[N_NODES];   // bucket fill ctr; zero at load; re-zeroed by fusedU
__device__ __align__(16) int   g_deg[N_NODES];   // indegree (REDG);  zero at load; re-zeroed by fusedU
__device__ __align__(16) int   g_bkt[(size_t)N_NODES * BKT];
__device__ __align__(16) __half g_H0h[(size_t)N_NODES * HID];  // (H0+b1)*rdeg, fp16
__device__ __align__(16) float g_Z[N_NODES * 2];
__device__ __align__(16) __half g_Af[(size_t)M_PAD * F_IN];    // feature fp16
__device__ __align__(16) __half g_Bf[HID * F_IN];              // W1^T fp16 [n][k]

// ---------------- static-init stream/event resources ----------------
struct ForkRes {
    cudaStream_t s = nullptr;
    cudaEvent_t e1 = nullptr, e2 = nullptr, e3 = nullptr;
    bool ok = false;
    ForkRes() {
        if (cudaStreamCreateWithFlags(&s, cudaStreamNonBlocking) == cudaSuccess &&
            cudaEventCreateWithFlags(&e1, cudaEventDisableTiming) == cudaSuccess &&
            cudaEventCreateWithFlags(&e2, cudaEventDisableTiming) == cudaSuccess &&
            cudaEventCreateWithFlags(&e3, cudaEventDisableTiming) == cudaSuccess)
            ok = true;
    }
};
static ForkRes g_fork;

// ---------------- helpers ----------------
#define LDSM_X4(r0, r1, r2, r3, addr) \
    asm volatile("ldmatrix.sync.aligned.m8n8.x4.shared.b16 {%0,%1,%2,%3}, [%4];" \
        : "=r"(r0), "=r"(r1), "=r"(r2), "=r"(r3) : "r"(addr))
#define LDSM_X2(r0, r1, addr) \
    asm volatile("ldmatrix.sync.aligned.m8n8.x2.shared.b16 {%0,%1}, [%2];" \
        : "=r"(r0), "=r"(r1) : "r"(addr))
#define MMA_F16(d0, d1, d2, d3, a0, a1, a2, a3, b0, b1) \
    asm volatile("mma.sync.aligned.m16n8k16.row.col.f32.f16.f16.f32 " \
        "{%0,%1,%2,%3}, {%4,%5,%6,%7}, {%8,%9}, {%0,%1,%2,%3};" \
        : "+f"(d0), "+f"(d1), "+f"(d2), "+f"(d3) \
        : "r"(a0), "r"(a1), "r"(a2), "r"(a3), "r"(b0), "r"(b1))
#define CP16(saddr, gptr) \
    asm volatile("cp.async.cg.shared.global [%0], [%1], 16;" :: "r"(saddr), "l"(gptr))
#define CP_COMMIT() asm volatile("cp.async.commit_group;" ::: "memory")
#define CP_WAIT1()  asm volatile("cp.async.wait_group 1;" ::: "memory")

// ---------------- degree (no return value -> REDG) ----------------
__global__ void deg_kernel(const int* __restrict__ ei) {
    int e = blockIdx.x * blockDim.x + threadIdx.x;
    if (e >= N_EDGES) return;
    atomicAdd(&g_deg[ei[N_EDGES + e]], 1);
}

// ---------------- bucket scatter ----------------
__global__ void scatter_kernel(const int* __restrict__ ei) {
    int e = blockIdx.x * blockDim.x + threadIdx.x;
    if (e >= N_EDGES) return;
    int s = ei[e];
    int d = ei[N_EDGES + e];
    int pos = atomicAdd(&g_pos[d], 1);
    if (pos < BKT) g_bkt[(size_t)d * BKT + pos] = s;
}

// ---------------- prep: fp16 A + transpose fp16 W1 ----------------
__global__ void prep_kernel(const float* __restrict__ A, const float* __restrict__ W1) {
    int tid = blockIdx.x * blockDim.x + threadIdx.x;
    if (tid < (N_NODES * F_IN) / 8) {
        int idx8 = tid * 8;
        const float* p = A + idx8;
        float4 v0 = *(const float4*)p;
        float4 v1 = *(const float4*)(p + 4);
        uint32_t w[4];
        __half2 h;
        h = __floats2half2_rn(v0.x, v0.y); w[0] = *(uint32_t*)&h;
        h = __floats2half2_rn(v0.z, v0.w); w[1] = *(uint32_t*)&h;
        h = __floats2half2_rn(v1.x, v1.y); w[2] = *(uint32_t*)&h;
        h = __floats2half2_rn(v1.z, v1.w); w[3] = *(uint32_t*)&h;
        *(uint4*)(g_Af + idx8) = make_uint4(w[0], w[1], w[2], w[3]);
    }
    if (tid < (F_IN * HID) / 8) {
        int n = tid & 255;
        int kb = (tid >> 8) * 8;
        uint32_t w[4];
        #pragma unroll
        for (int q = 0; q < 4; q++) {
            float x0 = W1[(size_t)(kb + 2 * q) * HID + n];
            float x1 = W1[(size_t)(kb + 2 * q + 1) * HID + n];
            __half2 h = __floats2half2_rn(x0, x1);
            w[q] = *(uint32_t*)&h;
        }
        *(uint4*)(g_Bf + (size_t)n * F_IN + kb) = make_uint4(w[0], w[1], w[2], w[3]);
    }
}

// ---------------- HMMA fp16 GEMM: CTA tile 64x128, grid (2,157) ----------------
#define ROWB 80
#define S_A 0
#define S_B 5120
#define STG 15360

__global__ __launch_bounds__(256, 2) void gemm_mma_kernel(const float* __restrict__ bias) {
    extern __shared__ __align__(128) char sm[];
    uint32_t sbase = (uint32_t)__cvta_generic_to_shared(sm);

    const int M = N_NODES;
    int tid = threadIdx.x;
    int wid = tid >> 5;
    int lane = tid & 31;
    int wm = wid >> 2;
    int wn = wid & 3;
    int bm = blockIdx.y * 64;
    int bn = blockIdx.x * 128;

    float acc[2][4][4];
    #pragma unroll
    for (int i = 0; i < 2; i++)
        #pragma unroll
        for (int j = 0; j < 4; j++)
            #pragma unroll
            for (int r = 0; r < 4; r++) acc[i][j][r] = 0.f;

    auto load_stage = [&](int c, int s) {
        int kb = c * 64;
        uint32_t sb = sbase + s * STG;
        const char* gA = (const char*)g_Af + (size_t)bm * 1024 + kb;
        const char* gB = (const char*)g_Bf + (size_t)bn * 1024 + kb;
        {
            int r = tid >> 2, j = tid & 3;
            CP16(sb + S_A + r * ROWB + j * 16, gA + (size_t)r * 1024 + j * 16);
        }
        #pragma unroll
        for (int i = 0; i < 2; i++) {
            int idx = tid + 256 * i;
            int r = idx >> 2, j = idx & 3;
            CP16(sb + S_B + r * ROWB + j * 16, gB + (size_t)r * 1024 + j * 16);
        }
    };

    load_stage(0, 0);
    CP_COMMIT();

    for (int c = 0; c < 16; c++) {
        int s = c & 1;
        if (c + 1 < 16) load_stage(c + 1, (c + 1) & 1);
        CP_COMMIT();
        CP_WAIT1();
        __syncthreads();

        uint32_t stb = sbase + s * STG;
        #pragma unroll
        for (int ks = 0; ks < 2; ks++) {
            int kbyte = ks * 32;
            uint32_t bf[4][2];
            #pragma unroll
            for (int na = 0; na < 4; na++) {
                uint32_t ad = stb + S_B +
                    (uint32_t)((wn * 32 + na * 8 + (lane & 7)) * ROWB + kbyte + ((lane >> 3) & 1) * 16);
                LDSM_X2(bf[na][0], bf[na][1], ad);
            }
            #pragma unroll
            for (int ma = 0; ma < 2; ma++) {
                uint32_t aad = stb + S_A +
                    (uint32_t)((wm * 32 + ma * 16 + (lane & 15)) * ROWB + kbyte + (lane >> 4) * 16);
                uint32_t a0, a1, a2, a3;
                LDSM_X4(a0, a1, a2, a3, aad);
                #pragma unroll
                for (int na = 0; na < 4; na++) {
                    MMA_F16(acc[ma][na][0], acc[ma][na][1], acc[ma][na][2], acc[ma][na][3],
                            a0, a1, a2, a3, bf[na][0], bf[na][1]);
                }
            }
        }
        __syncthreads();
    }

    // epilogue: (acc + bias) * rdeg[row], store fp16
    #pragma unroll
    for (int ma = 0; ma < 2; ma++) {
        int grow0 = bm + wm * 32 + ma * 16 + (lane >> 2);
        int grow1 = grow0 + 8;
        float r0 = (grow0 < M) ? rsqrtf(fmaxf((float)g_deg[grow0], 1.0f)) : 0.f;
        float r1 = (grow1 < M) ? rsqrtf(fmaxf((float)g_deg[grow1], 1.0f)) : 0.f;
        #pragma unroll
        for (int na = 0; na < 4; na++) {
            int col = bn + wn * 32 + na * 8 + (lane & 3) * 2;
            float2 bv = *(const float2*)(bias + col);
            if (grow0 < M) {
                __half2 o = __floats2half2_rn((acc[ma][na][0] + bv.x) * r0,
                                              (acc[ma][na][1] + bv.y) * r0);
                *(__half2*)(g_H0h + (size_t)grow0 * HID + col) = o;
            }
            if (grow1 < M) {
                __half2 o = __floats2half2_rn((acc[ma][na][2] + bv.x) * r1,
                                              (acc[ma][na][3] + bv.y) * r1);
                *(__half2*)(g_H0h + (size_t)grow1 * HID + col) = o;
            }
        }
    }
}

// ---------------- fusedZ: 2 warps/node, 8-edge unroll (MLP 8) ----------------
__global__ __launch_bounds__(256) void fusedZ_kernel(const float* __restrict__ W2,
                                                     const float* __restrict__ b2) {
    __shared__ float sZ[8][2];
    int wid = threadIdx.x >> 5;
    int lane = threadIdx.x & 31;
    int gwarp = blockIdx.x * 8 + wid;
    int node = gwarp >> 1;
    int half = gwarp & 1;
    if (node >= N_NODES) return;

    int cnt = g_pos[node];
    float rdd = rsqrtf(fmaxf((float)cnt, 1.0f));
    if (cnt > BKT) cnt = BKT;
    const int* bkt = g_bkt + (size_t)node * BKT;

    int c0 = half * 128 + 4 * lane;
    float w0[4], w1[4];
    #pragma unroll
    for (int j = 0; j < 4; j++) {
        w0[j] = __ldg(&W2[(c0 + j) * 2 + 0]);
        w1[j] = __ldg(&W2[(c0 + j) * 2 + 1]);
    }
    size_t lane_off = (size_t)half * 128 + 4 * lane;

    float acc[4] = {};
    int p = 0;
    for (; p + 8 <= cnt; p += 8) {
        uint4 i0 = *(const uint4*)(bkt + p);
        uint4 i1 = *(const uint4*)(bkt + p + 4);
        uint2 v0 = *(const uint2*)(g_H0h + (size_t)i0.x * HID + lane_off);
        uint2 v1 = *(const uint2*)(g_H0h + (size_t)i0.y * HID + lane_off);
        uint2 v2 = *(const uint2*)(g_H0h + (size_t)i0.z * HID + lane_off);
        uint2 v3 = *(const uint2*)(g_H0h + (size_t)i0.w * HID + lane_off);
        uint2 v4 = *(const uint2*)(g_H0h + (size_t)i1.x * HID + lane_off);
        uint2 v5 = *(const uint2*)(g_H0h + (size_t)i1.y * HID + lane_off);
        uint2 v6 = *(const uint2*)(g_H0h + (size_t)i1.z * HID + lane_off);
        uint2 v7 = *(const uint2*)(g_H0h + (size_t)i1.w * HID + lane_off);
        // group 1 (v0..v3): depth-2 hadd2 then fp32
        __half2 ax = __hadd2(__hadd2(*(const __half2*)&v0.x, *(const __half2*)&v1.x),
                             __hadd2(*(const __half2*)&v2.x, *(const __half2*)&v3.x));
        __half2 ay = __hadd2(__hadd2(*(const __half2*)&v0.y, *(const __half2*)&v1.y),
                             __hadd2(*(const __half2*)&v2.y, *(const __half2*)&v3.y));
        // group 2 (v4..v7)
        __half2 bx = __hadd2(__hadd2(*(const __half2*)&v4.x, *(const __half2*)&v5.x),
                             __hadd2(*(const __half2*)&v6.x, *(const __half2*)&v7.x));
        __half2 by = __hadd2(__hadd2(*(const __half2*)&v4.y, *(const __half2*)&v5.y),
                             __hadd2(*(const __half2*)&v6.y, *(const __half2*)&v7.y));
        float2 fax = __half22float2(ax);
        float2 fay = __half22float2(ay);
        float2 fbx = __half22float2(bx);
        float2 fby = __half22float2(by);
        acc[0] += fax.x + fbx.x;
        acc[1] += fax.y + fbx.y;
        acc[2] += fay.x + fby.x;
        acc[3] += fay.y + fby.y;
    }
    for (; p + 4 <= cnt; p += 4) {
        uint4 i0 = *(const uint4*)(bkt + p);
        uint2 v0 = *(const uint2*)(g_H0h + (size_t)i0.x * HID + lane_off);
        uint2 v1 = *(const uint2*)(g_H0h + (size_t)i0.y * HID + lane_off);
        uint2 v2 = *(const uint2*)(g_H0h + (size_t)i0.z * HID + lane_off);
        uint2 v3 = *(const uint2*)(g_H0h + (size_t)i0.w * HID + lane_off);
        __half2 ax = __hadd2(__hadd2(*(const __half2*)&v0.x, *(const __half2*)&v1.x),
                             __hadd2(*(const __half2*)&v2.x, *(const __half2*)&v3.x));
        __half2 ay = __hadd2(__hadd2(*(const __half2*)&v0.y, *(const __half2*)&v1.y),
                             __hadd2(*(const __half2*)&v2.y, *(const __half2*)&v3.y));
        float2 fax = __half22float2(ax);
        float2 fay = __half22float2(ay);
        acc[0] += fax.x;
        acc[1] += fax.y;
        acc[2] += fay.x;
        acc[3] += fay.y;
    }
    for (; p < cnt; p++) {
        int s0 = bkt[p];
        uint2 v0 = *(const uint2*)(g_H0h + (size_t)s0 * HID + lane_off);
        float2 f0a = __half22float2(*(const __half2*)&v0.x);
        float2 f0b = __half22float2(*(const __half2*)&v0.y);
        acc[0] += f0a.x;
        acc[1] += f0a.y;
        acc[2] += f0b.x;
        acc[3] += f0b.y;
    }

    float z0 = 0.f, z1 = 0.f;
    #pragma unroll
    for (int j = 0; j < 4; j++) {
        float x = fmaxf(acc[j] * rdd, 0.f);
        z0 += x * w0[j];
        z1 += x * w1[j];
    }
    #pragma unroll
    for (int o = 16; o; o >>= 1) {
        z0 += __shfl_down_sync(0xFFFFFFFFu, z0, o);
        z1 += __shfl_down_sync(0xFFFFFFFFu, z1, o);
    }
    if (lane == 0) {
        sZ[wid][0] = z0;
        sZ[wid][1] = z1;
    }
    __syncthreads();
    if (half == 0 && lane == 0) {
        float t0 = sZ[wid][0] + sZ[wid + 1][0];
        float t1 = sZ[wid][1] + sZ[wid + 1][1];
        g_Z[2 * node + 0] = (t0 + b2[0]) * rdd;
        g_Z[2 * node + 1] = (t1 + b2[1]) * rdd;
    }
}

// ---------------- fusedU + lift + projection; re-zeroes g_pos & g_deg ----------------
__global__ __launch_bounds__(256) void fusedU_kernel(const float* __restrict__ scale,
                                                     float* __restrict__ out) {
    int gw = (blockIdx.x * blockDim.x + threadIdx.x) >> 5;
    int lane = threadIdx.x & 31;
    if (gw >= N_NODES) return;

    int cnt = g_pos[gw];
    float rdd = rsqrtf(fmaxf((float)cnt, 1.0f));
    if (cnt > BKT) cnt = BKT;
    const int* bkt = g_bkt + (size_t)gw * BKT;
    __syncwarp();
    if (lane == 0) {
        g_pos[gw] = 0;
        g_deg[gw] = 0;
    }

    float u0 = 0.f, u1 = 0.f;
    for (int p = lane; p < cnt; p += 32) {
        int s = bkt[p];
        float2 z = *(const float2*)(g_Z + 2 * s);
        u0 += z.x;
        u1 += z.y;
    }
    #pragma unroll
    for (int o = 16; o; o >>= 1) {
        u0 += __shfl_down_sync(0xFFFFFFFFu, u0, o);
        u1 += __shfl_down_sync(0xFFFFFFFFu, u1, o);
    }
    if (lane == 0) {
        u0 *= rdd;
        u1 *= rdd;
        float un = sqrtf(u0 * u0 + u1 * u1);
        un = fmaxf(un, 1e-15f);
        float ch = coshf(un);
        float sh = sinhf(un);
        float inv = 1.0f / (un * (1.0f + ch));
        float p0 = sh * u0 * inv;
        float p1 = sh * u1 * inv;
        float pn = fmaxf(sqrtf(p0 * p0 + p1 * p1), 1e-12f);
        const float MIN_SCALE = 2.0f * (0.999f / 3.0f);
        const float MAX_SCALE = 0.999f;
        float s = fminf(fmaxf(scale[0], MIN_SCALE), MAX_SCALE);
        p0 = p0 / pn * s;
        p1 = p1 / pn * s;
        float nrm = fmaxf(sqrtf(p0 * p0 + p1 * p1), 1e-15f);
        float maxnorm = 1.0f - 1e-15f;
        if (nrm > maxnorm) {
            p0 = p0 / nrm * maxnorm;
            p1 = p1 / nrm * maxnorm;
        }
        out[2 * gw + 0] = p0;
        out[2 * gw + 1] = p1;
    }
}

// ---------------- launch ----------------
extern "C" void kernel_launch(void* const* d_in, const int* in_sizes, int n_in,
                              void* d_out, int out_size) {
    const float* feature = (const float*)d_in[0];
    const int* ei = (const int*)d_in[1];
    const float* W1 = (const float*)d_in[2];
    const float* b1 = (const float*)d_in[3];
    const float* W2 = (const float*)d_in[4];
    const float* b2 = (const float*)d_in[5];
    const float* scale = (const float*)d_in[6];
    float* out = (float*)d_out;

    cudaFuncSetAttribute(gemm_mma_kernel,
                         cudaFuncAttributeMaxDynamicSharedMemorySize, 2 * STG);

    dim3 gemm_grid(HID / 128, (N_NODES + 63) / 64);   // (2, 157)
    int prep_blocks = ((N_NODES * F_IN / 8) + 255) / 256;
    int edge_blocks = (N_EDGES + 255) / 256;

    if (g_fork.ok) {
        // main: deg -> scatter ; side: prep (immediately), wait(deg), gemm
        cudaEventRecord(g_fork.e1, 0);
        cudaStreamWaitEvent(g_fork.s, g_fork.e1, 0);
        prep_kernel<<<prep_blocks, 256, 0, g_fork.s>>>(feature, W1);

        deg_kernel<<<edge_blocks, 256>>>(ei);
        cudaEventRecord(g_fork.e3, 0);
        scatter_kernel<<<edge_blocks, 256>>>(ei);

        cudaStreamWaitEvent(g_fork.s, g_fork.e3, 0);
        gemm_mma_kernel<<<gemm_grid, 256, 2 * STG, g_fork.s>>>(b1);
        cudaEventRecord(g_fork.e2, g_fork.s);
        cudaStreamWaitEvent(0, g_fork.e2, 0);
    } else {
        deg_kernel<<<edge_blocks, 256>>>(ei);
        prep_kernel<<<prep_blocks, 256>>>(feature, W1);
        scatter_kernel<<<edge_blocks, 256>>>(ei);
        gemm_mma_kernel<<<gemm_grid, 256, 2 * STG>>>(b1);
    }

    fusedZ_kernel<<<(N_NODES * 2 + 7) / 8, 256>>>(W2, b2);
    fusedU_kernel<<<(N_NODES * 32 + 255) / 256, 256>>>(scale, out);
}

// round 15
// speedup vs baseline: 1.0612x; 1.0034x over previous
#include <cuda_runtime.h>
#include <cuda_fp16.h>
#include <cstdint>

#define N_NODES 10000
#define N_EDGES 320000
#define F_IN 512
#define HID 256
#define M_PAD 10112
#define BKT 128

// ---------------- device scratch ----------------
__device__ __align__(16) int   g_pos[N_NODES];   // bucket fill ctr; zero at load; re-zeroed by fusedU
__device__ __align__(16) int   g_deg[N_NODES];   // indegree; zero at load; re-zeroed by fusedU
__device__ __align__(16) int   g_bkt[(size_t)N_NODES * BKT];
__device__ __align__(16) __half g_H0h[(size_t)N_NODES * HID];  // (H0+b1)*rdeg, fp16
__device__ __align__(16) float g_Z[N_NODES * 2];
__device__ __align__(16) __half g_Af[(size_t)M_PAD * F_IN];    // feature fp16
__device__ __align__(16) __half g_Bf[HID * F_IN];              // W1^T fp16 [n][k]

// ---------------- static-init stream/event resources ----------------
struct ForkRes {
    cudaStream_t s = nullptr;
    cudaEvent_t e1 = nullptr, e2 = nullptr, e3 = nullptr;
    bool ok = false;
    ForkRes() {
        if (cudaStreamCreateWithFlags(&s, cudaStreamNonBlocking) == cudaSuccess &&
            cudaEventCreateWithFlags(&e1, cudaEventDisableTiming) == cudaSuccess &&
            cudaEventCreateWithFlags(&e2, cudaEventDisableTiming) == cudaSuccess &&
            cudaEventCreateWithFlags(&e3, cudaEventDisableTiming) == cudaSuccess)
            ok = true;
    }
};
static ForkRes g_fork;

// ---------------- helpers ----------------
#define LDSM_X4(r0, r1, r2, r3, addr) \
    asm volatile("ldmatrix.sync.aligned.m8n8.x4.shared.b16 {%0,%1,%2,%3}, [%4];" \
        : "=r"(r0), "=r"(r1), "=r"(r2), "=r"(r3) : "r"(addr))
#define LDSM_X2(r0, r1, addr) \
    asm volatile("ldmatrix.sync.aligned.m8n8.x2.shared.b16 {%0,%1}, [%2];" \
        : "=r"(r0), "=r"(r1) : "r"(addr))
#define MMA_F16(d0, d1, d2, d3, a0, a1, a2, a3, b0, b1) \
    asm volatile("mma.sync.aligned.m16n8k16.row.col.f32.f16.f16.f32 " \
        "{%0,%1,%2,%3}, {%4,%5,%6,%7}, {%8,%9}, {%0,%1,%2,%3};" \
        : "+f"(d0), "+f"(d1), "+f"(d2), "+f"(d3) \
        : "r"(a0), "r"(a1), "r"(a2), "r"(a3), "r"(b0), "r"(b1))
#define CP16(saddr, gptr) \
    asm volatile("cp.async.cg.shared.global [%0], [%1], 16;" :: "r"(saddr), "l"(gptr))
#define CP_COMMIT() asm volatile("cp.async.commit_group;" ::: "memory")
#define CP_WAIT_1() asm volatile("cp.async.wait_group 1;" ::: "memory")

// ---------------- degree ----------------
__global__ void deg_kernel(const int* __restrict__ ei) {
    int e = blockIdx.x * blockDim.x + threadIdx.x;
    if (e >= N_EDGES) return;
    atomicAdd(&g_deg[ei[N_EDGES + e]], 1);
}

// ---------------- bucket scatter ----------------
__global__ void scatter_kernel(const int* __restrict__ ei) {
    int e = blockIdx.x * blockDim.x + threadIdx.x;
    if (e >= N_EDGES) return;
    int s = ei[e];
    int d = ei[N_EDGES + e];
    int pos = atomicAdd(&g_pos[d], 1);
    if (pos < BKT) g_bkt[(size_t)d * BKT + pos] = s;
}

// ---------------- prep: fp16 A + transpose fp16 W1 ----------------
__global__ void prep_kernel(const float* __restrict__ A, const float* __restrict__ W1) {
    int tid = blockIdx.x * blockDim.x + threadIdx.x;
    if (tid < (N_NODES * F_IN) / 8) {
        int idx8 = tid * 8;
        const float* p = A + idx8;
        float4 v0 = *(const float4*)p;
        float4 v1 = *(const float4*)(p + 4);
        uint32_t w[4];
        __half2 h;
        h = __floats2half2_rn(v0.x, v0.y); w[0] = *(uint32_t*)&h;
        h = __floats2half2_rn(v0.z, v0.w); w[1] = *(uint32_t*)&h;
        h = __floats2half2_rn(v1.x, v1.y); w[2] = *(uint32_t*)&h;
        h = __floats2half2_rn(v1.z, v1.w); w[3] = *(uint32_t*)&h;
        *(uint4*)(g_Af + idx8) = make_uint4(w[0], w[1], w[2], w[3]);
    }
    if (tid < (F_IN * HID) / 8) {
        int n = tid & 255;
        int kb = (tid >> 8) * 8;
        uint32_t w[4];
        #pragma unroll
        for (int q = 0; q < 4; q++) {
            float x0 = W1[(size_t)(kb + 2 * q) * HID + n];
            float x1 = W1[(size_t)(kb + 2 * q + 1) * HID + n];
            __half2 h = __floats2half2_rn(x0, x1);
            w[q] = *(uint32_t*)&h;
        }
        *(uint4*)(g_Bf + (size_t)n * F_IN + kb) = make_uint4(w[0], w[1], w[2], w[3]);
    }
}

// ---------------- HMMA fp16 GEMM: 64x128 tile, 3-stage cp.async, 1 sync/chunk ----------------
// K chunks of 64 elements (128B); 8 chunks. ROWB=144 (odd multiple of 16B -> ldsm conflict-free).
// Stage: A 64*144 + B 128*144 = 27648 B; 3 stages = 82944 B dynamic smem.
#define ROWB 144
#define S_A 0
#define S_B 9216
#define STG 27648
#define NCHUNK 8

__global__ __launch_bounds__(256, 2) void gemm_mma_kernel(const float* __restrict__ bias) {
    extern __shared__ __align__(128) char sm[];
    uint32_t sbase = (uint32_t)__cvta_generic_to_shared(sm);

    const int M = N_NODES;
    int tid = threadIdx.x;
    int wid = tid >> 5;
    int lane = tid & 31;
    int wm = wid >> 2;
    int wn = wid & 3;
    int bm = blockIdx.y * 64;
    int bn = blockIdx.x * 128;

    float acc[2][4][4];
    #pragma unroll
    for (int i = 0; i < 2; i++)
        #pragma unroll
        for (int j = 0; j < 4; j++)
            #pragma unroll
            for (int r = 0; r < 4; r++) acc[i][j][r] = 0.f;

    auto load_stage = [&](int c) {
        int slot = c % 3;
        int kb = c * 128;                       // byte offset into 1024B rows
        uint32_t sb = sbase + slot * STG;
        const char* gA = (const char*)g_Af + (size_t)bm * 1024 + kb;
        const char* gB = (const char*)g_Bf + (size_t)bn * 1024 + kb;
        // A: 64 rows x 8 units = 512 units, 2 per thread
        #pragma unroll
        for (int i = 0; i < 2; i++) {
            int idx = tid + 256 * i;
            int r = idx >> 3, j = idx & 7;
            CP16(sb + S_A + r * ROWB + j * 16, gA + (size_t)r * 1024 + j * 16);
        }
        // B: 128 rows x 8 units = 1024 units, 4 per thread
        #pragma unroll
        for (int i = 0; i < 4; i++) {
            int idx = tid + 256 * i;
            int r = idx >> 3, j = idx & 7;
            CP16(sb + S_B + r * ROWB + j * 16, gB + (size_t)r * 1024 + j * 16);
        }
    };

    // preload stages 0,1 (2 commit groups)
    load_stage(0);
    CP_COMMIT();
    load_stage(1);
    CP_COMMIT();

    for (int c = 0; c < NCHUNK; c++) {
        CP_WAIT_1();            // stage c complete (<=1 group pending)
        __syncthreads();        // all warps done reading slot (c-1)%3 AND see stage c data
        if (c + 2 < NCHUNK) load_stage(c + 2);
        CP_COMMIT();

        uint32_t stb = sbase + (c % 3) * STG;
        #pragma unroll
        for (int ks = 0; ks < 4; ks++) {
            int kbyte = ks * 32;
            uint32_t bf[4][2];
            #pragma unroll
            for (int na = 0; na < 4; na++) {
                uint32_t ad = stb + S_B +
                    (uint32_t)((wn * 32 + na * 8 + (lane & 7)) * ROWB + kbyte + ((lane >> 3) & 1) * 16);
                LDSM_X2(bf[na][0], bf[na][1], ad);
            }
            #pragma unroll
            for (int ma = 0; ma < 2; ma++) {
                uint32_t aad = stb + S_A +
                    (uint32_t)((wm * 32 + ma * 16 + (lane & 15)) * ROWB + kbyte + (lane >> 4) * 16);
                uint32_t a0, a1, a2, a3;
                LDSM_X4(a0, a1, a2, a3, aad);
                #pragma unroll
                for (int na = 0; na < 4; na++) {
                    MMA_F16(acc[ma][na][0], acc[ma][na][1], acc[ma][na][2], acc[ma][na][3],
                            a0, a1, a2, a3, bf[na][0], bf[na][1]);
                }
            }
        }
    }

    // epilogue: (acc + bias) * rdeg[row], store fp16
    #pragma unroll
    for (int ma = 0; ma < 2; ma++) {
        int grow0 = bm + wm * 32 + ma * 16 + (lane >> 2);
        int grow1 = grow0 + 8;
        float r0 = (grow0 < M) ? rsqrtf(fmaxf((float)g_deg[grow0], 1.0f)) : 0.f;
        float r1 = (grow1 < M) ? rsqrtf(fmaxf((float)g_deg[grow1], 1.0f)) : 0.f;
        #pragma unroll
        for (int na = 0; na < 4; na++) {
            int col = bn + wn * 32 + na * 8 + (lane & 3) * 2;
            float2 bv = *(const float2*)(bias + col);
            if (grow0 < M) {
                __half2 o = __floats2half2_rn((acc[ma][na][0] + bv.x) * r0,
                                              (acc[ma][na][1] + bv.y) * r0);
                *(__half2*)(g_H0h + (size_t)grow0 * HID + col) = o;
            }
            if (grow1 < M) {
                __half2 o = __floats2half2_rn((acc[ma][na][2] + bv.x) * r1,
                                              (acc[ma][na][3] + bv.y) * r1);
                *(__half2*)(g_H0h + (size_t)grow1 * HID + col) = o;
            }
        }
    }
}

// ---------------- fusedZ: 2 warps/node, 8-edge unroll ----------------
__global__ __launch_bounds__(256) void fusedZ_kernel(const float* __restrict__ W2,
                                                     const float* __restrict__ b2) {
    __shared__ float sZ[8][2];
    int wid = threadIdx.x >> 5;
    int lane = threadIdx.x & 31;
    int gwarp = blockIdx.x * 8 + wid;
    int node = gwarp >> 1;
    int half = gwarp & 1;
    if (node >= N_NODES) return;

    int cnt = g_pos[node];
    float rdd = rsqrtf(fmaxf((float)cnt, 1.0f));
    if (cnt > BKT) cnt = BKT;
    const int* bkt = g_bkt + (size_t)node * BKT;

    int c0 = half * 128 + 4 * lane;
    float w0[4], w1[4];
    #pragma unroll
    for (int j = 0; j < 4; j++) {
        w0[j] = __ldg(&W2[(c0 + j) * 2 + 0]);
        w1[j] = __ldg(&W2[(c0 + j) * 2 + 1]);
    }
    size_t lane_off = (size_t)half * 128 + 4 * lane;

    float acc[4] = {};
    int p = 0;
    for (; p + 8 <= cnt; p += 8) {
        uint4 i0 = *(const uint4*)(bkt + p);
        uint4 i1 = *(const uint4*)(bkt + p + 4);
        uint2 v0 = *(const uint2*)(g_H0h + (size_t)i0.x * HID + lane_off);
        uint2 v1 = *(const uint2*)(g_H0h + (size_t)i0.y * HID + lane_off);
        uint2 v2 = *(const uint2*)(g_H0h + (size_t)i0.z * HID + lane_off);
        uint2 v3 = *(const uint2*)(g_H0h + (size_t)i0.w * HID + lane_off);
        uint2 v4 = *(const uint2*)(g_H0h + (size_t)i1.x * HID + lane_off);
        uint2 v5 = *(const uint2*)(g_H0h + (size_t)i1.y * HID + lane_off);
        uint2 v6 = *(const uint2*)(g_H0h + (size_t)i1.z * HID + lane_off);
        uint2 v7 = *(const uint2*)(g_H0h + (size_t)i1.w * HID + lane_off);
        __half2 ax = __hadd2(__hadd2(*(const __half2*)&v0.x, *(const __half2*)&v1.x),
                             __hadd2(*(const __half2*)&v2.x, *(const __half2*)&v3.x));
        __half2 ay = __hadd2(__hadd2(*(const __half2*)&v0.y, *(const __half2*)&v1.y),
                             __hadd2(*(const __half2*)&v2.y, *(const __half2*)&v3.y));
        __half2 bx = __hadd2(__hadd2(*(const __half2*)&v4.x, *(const __half2*)&v5.x),
                             __hadd2(*(const __half2*)&v6.x, *(const __half2*)&v7.x));
        __half2 by = __hadd2(__hadd2(*(const __half2*)&v4.y, *(const __half2*)&v5.y),
                             __hadd2(*(const __half2*)&v6.y, *(const __half2*)&v7.y));
        float2 fax = __half22float2(ax);
        float2 fay = __half22float2(ay);
        float2 fbx = __half22float2(bx);
        float2 fby = __half22float2(by);
        acc[0] += fax.x + fbx.x;
        acc[1] += fax.y + fbx.y;
        acc[2] += fay.x + fby.x;
        acc[3] += fay.y + fby.y;
    }
    for (; p + 4 <= cnt; p += 4) {
        uint4 i0 = *(const uint4*)(bkt + p);
        uint2 v0 = *(const uint2*)(g_H0h + (size_t)i0.x * HID + lane_off);
        uint2 v1 = *(const uint2*)(g_H0h + (size_t)i0.y * HID + lane_off);
        uint2 v2 = *(const uint2*)(g_H0h + (size_t)i0.z * HID + lane_off);
        uint2 v3 = *(const uint2*)(g_H0h + (size_t)i0.w * HID + lane_off);
        __half2 ax = __hadd2(__hadd2(*(const __half2*)&v0.x, *(const __half2*)&v1.x),
                             __hadd2(*(const __half2*)&v2.x, *(const __half2*)&v3.x));
        __half2 ay = __hadd2(__hadd2(*(const __half2*)&v0.y, *(const __half2*)&v1.y),
                             __hadd2(*(const __half2*)&v2.y, *(const __half2*)&v3.y));
        float2 fax = __half22float2(ax);
        float2 fay = __half22float2(ay);
        acc[0] += fax.x;
        acc[1] += fax.y;
        acc[2] += fay.x;
        acc[3] += fay.y;
    }
    for (; p < cnt; p++) {
        int s0 = bkt[p];
        uint2 v0 = *(const uint2*)(g_H0h + (size_t)s0 * HID + lane_off);
        float2 f0a = __half22float2(*(const __half2*)&v0.x);
        float2 f0b = __half22float2(*(const __half2*)&v0.y);
        acc[0] += f0a.x;
        acc[1] += f0a.y;
        acc[2] += f0b.x;
        acc[3] += f0b.y;
    }

    float z0 = 0.f, z1 = 0.f;
    #pragma unroll
    for (int j = 0; j < 4; j++) {
        float x = fmaxf(acc[j] * rdd, 0.f);
        z0 += x * w0[j];
        z1 += x * w1[j];
    }
    #pragma unroll
    for (int o = 16; o; o >>= 1) {
        z0 += __shfl_down_sync(0xFFFFFFFFu, z0, o);
        z1 += __shfl_down_sync(0xFFFFFFFFu, z1, o);
    }
    if (lane == 0) {
        sZ[wid][0] = z0;
        sZ[wid][1] = z1;
    }
    __syncthreads();
    if (half == 0 && lane == 0) {
        float t0 = sZ[wid][0] + sZ[wid + 1][0];
        float t1 = sZ[wid][1] + sZ[wid + 1][1];
        g_Z[2 * node + 0] = (t0 + b2[0]) * rdd;
        g_Z[2 * node + 1] = (t1 + b2[1]) * rdd;
    }
}

// ---------------- fusedU + lift + projection; re-zeroes g_pos & g_deg ----------------
__global__ __launch_bounds__(256) void fusedU_kernel(const float* __restrict__ scale,
                                                     float* __restrict__ out) {
    int gw = (blockIdx.x * blockDim.x + threadIdx.x) >> 5;
    int lane = threadIdx.x & 31;
    if (gw >= N_NODES) return;

    int cnt = g_pos[gw];
    float rdd = rsqrtf(fmaxf((float)cnt, 1.0f));
    if (cnt > BKT) cnt = BKT;
    const int* bkt = g_bkt + (size_t)gw * BKT;
    __syncwarp();
    if (lane == 0) {
        g_pos[gw] = 0;
        g_deg[gw] = 0;
    }

    float u0 = 0.f, u1 = 0.f;
    for (int p = lane; p < cnt; p += 32) {
        int s = bkt[p];
        float2 z = *(const float2*)(g_Z + 2 * s);
        u0 += z.x;
        u1 += z.y;
    }
    #pragma unroll
    for (int o = 16; o; o >>= 1) {
        u0 += __shfl_down_sync(0xFFFFFFFFu, u0, o);
        u1 += __shfl_down_sync(0xFFFFFFFFu, u1, o);
    }
    if (lane == 0) {
        u0 *= rdd;
        u1 *= rdd;
        float un = sqrtf(u0 * u0 + u1 * u1);
        un = fmaxf(un, 1e-15f);
        float ch = coshf(un);
        float sh = sinhf(un);
        float inv = 1.0f / (un * (1.0f + ch));
        float p0 = sh * u0 * inv;
        float p1 = sh * u1 * inv;
        float pn = fmaxf(sqrtf(p0 * p0 + p1 * p1), 1e-12f);
        const float MIN_SCALE = 2.0f * (0.999f / 3.0f);
        const float MAX_SCALE = 0.999f;
        float s = fminf(fmaxf(scale[0], MIN_SCALE), MAX_SCALE);
        p0 = p0 / pn * s;
        p1 = p1 / pn * s;
        float nrm = fmaxf(sqrtf(p0 * p0 + p1 * p1), 1e-15f);
        float maxnorm = 1.0f - 1e-15f;
        if (nrm > maxnorm) {
            p0 = p0 / nrm * maxnorm;
            p1 = p1 / nrm * maxnorm;
        }
        out[2 * gw + 0] = p0;
        out[2 * gw + 1] = p1;
    }
}

// ---------------- launch ----------------
extern "C" void kernel_launch(void* const* d_in, const int* in_sizes, int n_in,
                              void* d_out, int out_size) {
    const float* feature = (const float*)d_in[0];
    const int* ei = (const int*)d_in[1];
    const float* W1 = (const float*)d_in[2];
    const float* b1 = (const float*)d_in[3];
    const float* W2 = (const float*)d_in[4];
    const float* b2 = (const float*)d_in[5];
    const float* scale = (const float*)d_in[6];
    float* out = (float*)d_out;

    cudaFuncSetAttribute(gemm_mma_kernel,
                         cudaFuncAttributeMaxDynamicSharedMemorySize, 3 * STG);

    dim3 gemm_grid(HID / 128, (N_NODES + 63) / 64);   // (2, 157)
    int prep_blocks = ((N_NODES * F_IN / 8) + 255) / 256;
    int edge_blocks = (N_EDGES + 255) / 256;

    if (g_fork.ok) {
        // main: deg -> scatter ; side: prep (immediately), wait(deg), gemm
        cudaEventRecord(g_fork.e1, 0);
        cudaStreamWaitEvent(g_fork.s, g_fork.e1, 0);
        prep_kernel<<<prep_blocks, 256, 0, g_fork.s>>>(feature, W1);

        deg_kernel<<<edge_blocks, 256>>>(ei);
        cudaEventRecord(g_fork.e3, 0);
        scatter_kernel<<<edge_blocks, 256>>>(ei);

        cudaStreamWaitEvent(g_fork.s, g_fork.e3, 0);
        gemm_mma_kernel<<<gemm_grid, 256, 3 * STG, g_fork.s>>>(b1);
        cudaEventRecord(g_fork.e2, g_fork.s);
        cudaStreamWaitEvent(0, g_fork.e2, 0);
    } else {
        deg_kernel<<<edge_blocks, 256>>>(ei);
        prep_kernel<<<prep_blocks, 256>>>(feature, W1);
        scatter_kernel<<<edge_blocks, 256>>>(ei);
        gemm_mma_kernel<<<gemm_grid, 256, 3 * STG>>>(b1);
    }

    fusedZ_kernel<<<(N_NODES * 2 + 7) / 8, 256>>>(W2, b2);
    fusedU_kernel<<<(N_NODES * 32 + 255) / 256, 256>>>(scale, out);
}

// round 16
// speedup vs baseline: 1.0895x; 1.0267x over previous
#include <cuda_runtime.h>
#include <cuda_fp16.h>
#include <cstdint>

#define N_NODES 10000
#define N_EDGES 320000
#define F_IN 512
#define HID 256
#define M_PAD 10112
#define BKT 128

// ---------------- device scratch ----------------
__device__ __align__(16) int   g_pos[N_NODES];   // bucket fill ctr; zero at load; re-zeroed by fusedU
__device__ __align__(16) int   g_deg[N_NODES];   // indegree; zero at load; re-zeroed by fusedU
__device__ __align__(16) int   g_bkt[(size_t)N_NODES * BKT];
__device__ __align__(16) __half g_H0h[(size_t)N_NODES * HID];  // (H0+b1)*rdeg, fp16
__device__ __align__(16) float g_Z[N_NODES * 2];
__device__ __align__(16) __half g_Af[(size_t)M_PAD * F_IN];    // feature fp16
__device__ __align__(16) __half g_Bf[HID * F_IN];              // W1^T fp16 [n][k]

// ---------------- static-init stream/event resources ----------------
struct ForkRes {
    cudaStream_t s = nullptr;
    cudaEvent_t e1 = nullptr, e2 = nullptr, e3 = nullptr;
    bool ok = false;
    ForkRes() {
        if (cudaStreamCreateWithFlags(&s, cudaStreamNonBlocking) == cudaSuccess &&
            cudaEventCreateWithFlags(&e1, cudaEventDisableTiming) == cudaSuccess &&
            cudaEventCreateWithFlags(&e2, cudaEventDisableTiming) == cudaSuccess &&
            cudaEventCreateWithFlags(&e3, cudaEventDisableTiming) == cudaSuccess)
            ok = true;
    }
};
static ForkRes g_fork;

// ---------------- helpers ----------------
#define LDSM_X4(r0, r1, r2, r3, addr) \
    asm volatile("ldmatrix.sync.aligned.m8n8.x4.shared.b16 {%0,%1,%2,%3}, [%4];" \
        : "=r"(r0), "=r"(r1), "=r"(r2), "=r"(r3) : "r"(addr))
#define LDSM_X2(r0, r1, addr) \
    asm volatile("ldmatrix.sync.aligned.m8n8.x2.shared.b16 {%0,%1}, [%2];" \
        : "=r"(r0), "=r"(r1) : "r"(addr))
#define MMA_F16(d0, d1, d2, d3, a0, a1, a2, a3, b0, b1) \
    asm volatile("mma.sync.aligned.m16n8k16.row.col.f32.f16.f16.f32 " \
        "{%0,%1,%2,%3}, {%4,%5,%6,%7}, {%8,%9}, {%0,%1,%2,%3};" \
        : "+f"(d0), "+f"(d1), "+f"(d2), "+f"(d3) \
        : "r"(a0), "r"(a1), "r"(a2), "r"(a3), "r"(b0), "r"(b1))
#define CP16(saddr, gptr) \
    asm volatile("cp.async.cg.shared.global [%0], [%1], 16;" :: "r"(saddr), "l"(gptr))
#define CP_COMMIT() asm volatile("cp.async.commit_group;" ::: "memory")
#define CP_WAIT_1() asm volatile("cp.async.wait_group 1;" ::: "memory")

// ---------------- degree (4 edges/thread, MLP 4) ----------------
__global__ void deg_kernel(const int* __restrict__ ei) {
    int t = blockIdx.x * blockDim.x + threadIdx.x;
    if (t >= N_EDGES / 4) return;
    int4 d = *(const int4*)(ei + N_EDGES + t * 4);
    atomicAdd(&g_deg[d.x], 1);
    atomicAdd(&g_deg[d.y], 1);
    atomicAdd(&g_deg[d.z], 1);
    atomicAdd(&g_deg[d.w], 1);
}

// ---------------- bucket scatter ----------------
__global__ void scatter_kernel(const int* __restrict__ ei) {
    int e = blockIdx.x * blockDim.x + threadIdx.x;
    if (e >= N_EDGES) return;
    int s = ei[e];
    int d = ei[N_EDGES + e];
    int pos = atomicAdd(&g_pos[d], 1);
    if (pos < BKT) g_bkt[(size_t)d * BKT + pos] = s;
}

// ---------------- prep: fp16 A + transpose fp16 W1 ----------------
__global__ void prep_kernel(const float* __restrict__ A, const float* __restrict__ W1) {
    int tid = blockIdx.x * blockDim.x + threadIdx.x;
    if (tid < (N_NODES * F_IN) / 8) {
        int idx8 = tid * 8;
        const float* p = A + idx8;
        float4 v0 = *(const float4*)p;
        float4 v1 = *(const float4*)(p + 4);
        uint32_t w[4];
        __half2 h;
        h = __floats2half2_rn(v0.x, v0.y); w[0] = *(uint32_t*)&h;
        h = __floats2half2_rn(v0.z, v0.w); w[1] = *(uint32_t*)&h;
        h = __floats2half2_rn(v1.x, v1.y); w[2] = *(uint32_t*)&h;
        h = __floats2half2_rn(v1.z, v1.w); w[3] = *(uint32_t*)&h;
        *(uint4*)(g_Af + idx8) = make_uint4(w[0], w[1], w[2], w[3]);
    }
    if (tid < (F_IN * HID) / 8) {
        int n = tid & 255;
        int kb = (tid >> 8) * 8;
        uint32_t w[4];
        #pragma unroll
        for (int q = 0; q < 4; q++) {
            float x0 = W1[(size_t)(kb + 2 * q) * HID + n];
            float x1 = W1[(size_t)(kb + 2 * q + 1) * HID + n];
            __half2 h = __floats2half2_rn(x0, x1);
            w[q] = *(uint32_t*)&h;
        }
        *(uint4*)(g_Bf + (size_t)n * F_IN + kb) = make_uint4(w[0], w[1], w[2], w[3]);
    }
}

// ---------------- HMMA fp16 GEMM: 64x64 tile, 128 thr, 3-stage, grid (4,157) ----------------
// K chunks of 64 elements (128B); 8 chunks. ROWB=144 (ldsm conflict-free).
// Stage: A 64*144 + B 64*144 = 18432 B; 3 stages = 55296 B; 4 CTAs/SM.
#define ROWB 144
#define S_A 0
#define S_B 9216
#define STG 18432
#define NCHUNK 8

__global__ __launch_bounds__(128, 4) void gemm_mma_kernel(const float* __restrict__ bias) {
    extern __shared__ __align__(128) char sm[];
    uint32_t sbase = (uint32_t)__cvta_generic_to_shared(sm);

    const int M = N_NODES;
    int tid = threadIdx.x;
    int wid = tid >> 5;
    int lane = tid & 31;
    int wm = wid >> 1;       // 0..1 -> M offset 32*wm
    int wn = wid & 1;        // 0..1 -> N offset 32*wn
    int bm = blockIdx.y * 64;
    int bn = blockIdx.x * 64;

    float acc[2][4][4];
    #pragma unroll
    for (int i = 0; i < 2; i++)
        #pragma unroll
        for (int j = 0; j < 4; j++)
            #pragma unroll
            for (int r = 0; r < 4; r++) acc[i][j][r] = 0.f;

    auto load_stage = [&](int c) {
        int slot = c % 3;
        int kb = c * 128;
        uint32_t sb = sbase + slot * STG;
        const char* gA = (const char*)g_Af + (size_t)bm * 1024 + kb;
        const char* gB = (const char*)g_Bf + (size_t)bn * 1024 + kb;
        // A: 64 rows x 8 units = 512, 4 per thread; B same
        #pragma unroll
        for (int i = 0; i < 4; i++) {
            int idx = tid + 128 * i;
            int r = idx >> 3, j = idx & 7;
            CP16(sb + S_A + r * ROWB + j * 16, gA + (size_t)r * 1024 + j * 16);
            CP16(sb + S_B + r * ROWB + j * 16, gB + (size_t)r * 1024 + j * 16);
        }
    };

    load_stage(0);
    CP_COMMIT();
    load_stage(1);
    CP_COMMIT();

    for (int c = 0; c < NCHUNK; c++) {
        CP_WAIT_1();
        __syncthreads();
        if (c + 2 < NCHUNK) load_stage(c + 2);
        CP_COMMIT();

        uint32_t stb = sbase + (c % 3) * STG;
        #pragma unroll
        for (int ks = 0; ks < 4; ks++) {
            int kbyte = ks * 32;
            uint32_t bf[4][2];
            #pragma unroll
            for (int na = 0; na < 4; na++) {
                uint32_t ad = stb + S_B +
                    (uint32_t)((wn * 32 + na * 8 + (lane & 7)) * ROWB + kbyte + ((lane >> 3) & 1) * 16);
                LDSM_X2(bf[na][0], bf[na][1], ad);
            }
            #pragma unroll
            for (int ma = 0; ma < 2; ma++) {
                uint32_t aad = stb + S_A +
                    (uint32_t)((wm * 32 + ma * 16 + (lane & 15)) * ROWB + kbyte + (lane >> 4) * 16);
                uint32_t a0, a1, a2, a3;
                LDSM_X4(a0, a1, a2, a3, aad);
                #pragma unroll
                for (int na = 0; na < 4; na++) {
                    MMA_F16(acc[ma][na][0], acc[ma][na][1], acc[ma][na][2], acc[ma][na][3],
                            a0, a1, a2, a3, bf[na][0], bf[na][1]);
                }
            }
        }
    }

    // epilogue: (acc + bias) * rdeg[row], store fp16
    #pragma unroll
    for (int ma = 0; ma < 2; ma++) {
        int grow0 = bm + wm * 32 + ma * 16 + (lane >> 2);
        int grow1 = grow0 + 8;
        float r0 = (grow0 < M) ? rsqrtf(fmaxf((float)g_deg[grow0], 1.0f)) : 0.f;
        float r1 = (grow1 < M) ? rsqrtf(fmaxf((float)g_deg[grow1], 1.0f)) : 0.f;
        #pragma unroll
        for (int na = 0; na < 4; na++) {
            int col = bn + wn * 32 + na * 8 + (lane & 3) * 2;
            float2 bv = *(const float2*)(bias + col);
            if (grow0 < M) {
                __half2 o = __floats2half2_rn((acc[ma][na][0] + bv.x) * r0,
                                              (acc[ma][na][1] + bv.y) * r0);
                *(__half2*)(g_H0h + (size_t)grow0 * HID + col) = o;
            }
            if (grow1 < M) {
                __half2 o = __floats2half2_rn((acc[ma][na][2] + bv.x) * r1,
                                              (acc[ma][na][3] + bv.y) * r1);
                *(__half2*)(g_H0h + (size_t)grow1 * HID + col) = o;
            }
        }
    }
}

// ---------------- fusedZ: 2 warps/node, 16-edge unroll (MLP 16) ----------------
__global__ __launch_bounds__(256) void fusedZ_kernel(const float* __restrict__ W2,
                                                     const float* __restrict__ b2) {
    __shared__ float sZ[8][2];
    int wid = threadIdx.x >> 5;
    int lane = threadIdx.x & 31;
    int gwarp = blockIdx.x * 8 + wid;
    int node = gwarp >> 1;
    int half = gwarp & 1;
    if (node >= N_NODES) return;

    int cnt = g_pos[node];
    float rdd = rsqrtf(fmaxf((float)cnt, 1.0f));
    if (cnt > BKT) cnt = BKT;
    const int* bkt = g_bkt + (size_t)node * BKT;

    int c0 = half * 128 + 4 * lane;
    float w0[4], w1[4];
    #pragma unroll
    for (int j = 0; j < 4; j++) {
        w0[j] = __ldg(&W2[(c0 + j) * 2 + 0]);
        w1[j] = __ldg(&W2[(c0 + j) * 2 + 1]);
    }
    size_t lane_off = (size_t)half * 128 + 4 * lane;

    float acc[4] = {};
    int p = 0;
    for (; p + 16 <= cnt; p += 16) {
        uint4 ia = *(const uint4*)(bkt + p);
        uint4 ib = *(const uint4*)(bkt + p + 4);
        uint4 ic = *(const uint4*)(bkt + p + 8);
        uint4 id = *(const uint4*)(bkt + p + 12);
        uint2 v[16];
        v[0]  = *(const uint2*)(g_H0h + (size_t)ia.x * HID + lane_off);
        v[1]  = *(const uint2*)(g_H0h + (size_t)ia.y * HID + lane_off);
        v[2]  = *(const uint2*)(g_H0h + (size_t)ia.z * HID + lane_off);
        v[3]  = *(const uint2*)(g_H0h + (size_t)ia.w * HID + lane_off);
        v[4]  = *(const uint2*)(g_H0h + (size_t)ib.x * HID + lane_off);
        v[5]  = *(const uint2*)(g_H0h + (size_t)ib.y * HID + lane_off);
        v[6]  = *(const uint2*)(g_H0h + (size_t)ib.z * HID + lane_off);
        v[7]  = *(const uint2*)(g_H0h + (size_t)ib.w * HID + lane_off);
        v[8]  = *(const uint2*)(g_H0h + (size_t)ic.x * HID + lane_off);
        v[9]  = *(const uint2*)(g_H0h + (size_t)ic.y * HID + lane_off);
        v[10] = *(const uint2*)(g_H0h + (size_t)ic.z * HID + lane_off);
        v[11] = *(const uint2*)(g_H0h + (size_t)ic.w * HID + lane_off);
        v[12] = *(const uint2*)(g_H0h + (size_t)id.x * HID + lane_off);
        v[13] = *(const uint2*)(g_H0h + (size_t)id.y * HID + lane_off);
        v[14] = *(const uint2*)(g_H0h + (size_t)id.z * HID + lane_off);
        v[15] = *(const uint2*)(g_H0h + (size_t)id.w * HID + lane_off);
        #pragma unroll
        for (int g = 0; g < 4; g++) {
            const uint2* q = v + g * 4;
            __half2 gx = __hadd2(__hadd2(*(const __half2*)&q[0].x, *(const __half2*)&q[1].x),
                                 __hadd2(*(const __half2*)&q[2].x, *(const __half2*)&q[3].x));
            __half2 gy = __hadd2(__hadd2(*(const __half2*)&q[0].y, *(const __half2*)&q[1].y),
                                 __hadd2(*(const __half2*)&q[2].y, *(const __half2*)&q[3].y));
            float2 fx = __half22float2(gx);
            float2 fy = __half22float2(gy);
            acc[0] += fx.x;
            acc[1] += fx.y;
            acc[2] += fy.x;
            acc[3] += fy.y;
        }
    }
    for (; p + 4 <= cnt; p += 4) {
        uint4 i0 = *(const uint4*)(bkt + p);
        uint2 v0 = *(const uint2*)(g_H0h + (size_t)i0.x * HID + lane_off);
        uint2 v1 = *(const uint2*)(g_H0h + (size_t)i0.y * HID + lane_off);
        uint2 v2 = *(const uint2*)(g_H0h + (size_t)i0.z * HID + lane_off);
        uint2 v3 = *(const uint2*)(g_H0h + (size_t)i0.w * HID + lane_off);
        __half2 ax = __hadd2(__hadd2(*(const __half2*)&v0.x, *(const __half2*)&v1.x),
                             __hadd2(*(const __half2*)&v2.x, *(const __half2*)&v3.x));
        __half2 ay = __hadd2(__hadd2(*(const __half2*)&v0.y, *(const __half2*)&v1.y),
                             __hadd2(*(const __half2*)&v2.y, *(const __half2*)&v3.y));
        float2 fax = __half22float2(ax);
        float2 fay = __half22float2(ay);
        acc[0] += fax.x;
        acc[1] += fax.y;
        acc[2] += fay.x;
        acc[3] += fay.y;
    }
    for (; p < cnt; p++) {
        int s0 = bkt[p];
        uint2 v0 = *(const uint2*)(g_H0h + (size_t)s0 * HID + lane_off);
        float2 f0a = __half22float2(*(const __half2*)&v0.x);
        float2 f0b = __half22float2(*(const __half2*)&v0.y);
        acc[0] += f0a.x;
        acc[1] += f0a.y;
        acc[2] += f0b.x;
        acc[3] += f0b.y;
    }

    float z0 = 0.f, z1 = 0.f;
    #pragma unroll
    for (int j = 0; j < 4; j++) {
        float x = fmaxf(acc[j] * rdd, 0.f);
        z0 += x * w0[j];
        z1 += x * w1[j];
    }
    #pragma unroll
    for (int o = 16; o; o >>= 1) {
        z0 += __shfl_down_sync(0xFFFFFFFFu, z0, o);
        z1 += __shfl_down_sync(0xFFFFFFFFu, z1, o);
    }
    if (lane == 0) {
        sZ[wid][0] = z0;
        sZ[wid][1] = z1;
    }
    __syncthreads();
    if (half == 0 && lane == 0) {
        float t0 = sZ[wid][0] + sZ[wid + 1][0];
        float t1 = sZ[wid][1] + sZ[wid + 1][1];
        g_Z[2 * node + 0] = (t0 + b2[0]) * rdd;
        g_Z[2 * node + 1] = (t1 + b2[1]) * rdd;
    }
}

// ---------------- fusedU + lift + projection; re-zeroes g_pos & g_deg ----------------
__global__ __launch_bounds__(256) void fusedU_kernel(const float* __restrict__ scale,
                                                     float* __restrict__ out) {
    int gw = (blockIdx.x * blockDim.x + threadIdx.x) >> 5;
    int lane = threadIdx.x & 31;
    if (gw >= N_NODES) return;

    int cnt = g_pos[gw];
    float rdd = rsqrtf(fmaxf((float)cnt, 1.0f));
    if (cnt > BKT) cnt = BKT;
    const int* bkt = g_bkt + (size_t)gw * BKT;
    __syncwarp();
    if (lane == 0) {
        g_pos[gw] = 0;
        g_deg[gw] = 0;
    }

    float u0 = 0.f, u1 = 0.f;
    for (int p = lane; p < cnt; p += 32) {
        int s = bkt[p];
        float2 z = *(const float2*)(g_Z + 2 * s);
        u0 += z.x;
        u1 += z.y;
    }
    #pragma unroll
    for (int o = 16; o; o >>= 1) {
        u0 += __shfl_down_sync(0xFFFFFFFFu, u0, o);
        u1 += __shfl_down_sync(0xFFFFFFFFu, u1, o);
    }
    if (lane == 0) {
        u0 *= rdd;
        u1 *= rdd;
        float un = sqrtf(u0 * u0 + u1 * u1);
        un = fmaxf(un, 1e-15f);
        float ch = coshf(un);
        float sh = sinhf(un);
        float inv = 1.0f / (un * (1.0f + ch));
        float p0 = sh * u0 * inv;
        float p1 = sh * u1 * inv;
        float pn = fmaxf(sqrtf(p0 * p0 + p1 * p1), 1e-12f);
        const float MIN_SCALE = 2.0f * (0.999f / 3.0f);
        const float MAX_SCALE = 0.999f;
        float s = fminf(fmaxf(scale[0], MIN_SCALE), MAX_SCALE);
        p0 = p0 / pn * s;
        p1 = p1 / pn * s;
        float nrm = fmaxf(sqrtf(p0 * p0 + p1 * p1), 1e-15f);
        float maxnorm = 1.0f - 1e-15f;
        if (nrm > maxnorm) {
            p0 = p0 / nrm * maxnorm;
            p1 = p1 / nrm * maxnorm;
        }
        out[2 * gw + 0] = p0;
        out[2 * gw + 1] = p1;
    }
}

// ---------------- launch ----------------
extern "C" void kernel_launch(void* const* d_in, const int* in_sizes, int n_in,
                              void* d_out, int out_size) {
    const float* feature = (const float*)d_in[0];
    const int* ei = (const int*)d_in[1];
    const float* W1 = (const float*)d_in[2];
    const float* b1 = (const float*)d_in[3];
    const float* W2 = (const float*)d_in[4];
    const float* b2 = (const float*)d_in[5];
    const float* scale = (const float*)d_in[6];
    float* out = (float*)d_out;

    cudaFuncSetAttribute(gemm_mma_kernel,
                         cudaFuncAttributeMaxDynamicSharedMemorySize, 3 * STG);

    dim3 gemm_grid(HID / 64, (N_NODES + 63) / 64);   // (4, 157)
    int prep_blocks = ((N_NODES * F_IN / 8) + 255) / 256;
    int edge_blocks = (N_EDGES + 255) / 256;
    int deg_blocks = (N_EDGES / 4 + 255) / 256;

    if (g_fork.ok) {
        // main: deg -> scatter ; side: prep (immediately), wait(deg), gemm
        cudaEventRecord(g_fork.e1, 0);
        cudaStreamWaitEvent(g_fork.s, g_fork.e1, 0);
        prep_kernel<<<prep_blocks, 256, 0, g_fork.s>>>(feature, W1);

        deg_kernel<<<deg_blocks, 256>>>(ei);
        cudaEventRecord(g_fork.e3, 0);
        scatter_kernel<<<edge_blocks, 256>>>(ei);

        cudaStreamWaitEvent(g_fork.s, g_fork.e3, 0);
        gemm_mma_kernel<<<gemm_grid, 128, 3 * STG, g_fork.s>>>(b1);
        cudaEventRecord(g_fork.e2, g_fork.s);
        cudaStreamWaitEvent(0, g_fork.e2, 0);
    } else {
        deg_kernel<<<deg_blocks, 256>>>(ei);
        prep_kernel<<<prep_blocks, 256>>>(feature, W1);
        scatter_kernel<<<edge_blocks, 256>>>(ei);
        gemm_mma_kernel<<<gemm_grid, 128, 3 * STG>>>(b1);
    }

    fusedZ_kernel<<<(N_NODES * 2 + 7) / 8, 256>>>(W2, b2);
    fusedU_kernel<<<(N_NODES * 32 + 255) / 256, 256>>>(scale, out);
}